// round 11
// baseline (speedup 1.0000x reference)
#include <cuda_runtime.h>
#include <math.h>

#define VOCABN 30000
#define DN 100
#define RN 150
#define RWN 50
#define SN 50
#define CN 20
#define BN 256
#define LN 512
#define VR 8                      // vocab rows per k1-role block
#define K1BLOCKS (VOCABN / VR)    // 3750
#define K0BLOCKS 32
#define WIN 68                    // k2 shared window stride (272B)

typedef unsigned long long ull;

// ---- folded constants / tables (static device memory) ----
__device__ float g_Tv[VOCABN * RN];    // blended V embedding per vocab id
__device__ float g_Trw[VOCABN * SN];   // (Tv*Cvs)@Wrs1 + bs1 per vocab id
__device__ float g_wild[SN * SN];      // [s][t]
__device__ float g_S2cT[RN * SN];      // S2[t][r]*Cvs[r], stored [r][t]
__device__ float g_SC[CN * 200];       // [c][0:150]=C_embed*u | [c][150:200]=C_w*uw

// ---- packed f32x2 helpers ----
__device__ __forceinline__ ull FMA2(ull a, ull b, ull c) {
    ull d;
    asm("fma.rn.f32x2 %0, %1, %2, %3;" : "=l"(d) : "l"(a), "l"(b), "l"(c));
    return d;
}
__device__ __forceinline__ float HSUM2(ull a, ull b) {
    union { ull u; float2 f; } x, y;
    x.u = a; y.u = b;
    return (x.f.x + x.f.y) + (y.f.x + y.f.y);
}
__device__ __forceinline__ ull PACK2(float a, float b) {
    union { ull u; float2 f; } x;
    x.f = make_float2(a, b);
    return x.u;
}
__device__ __forceinline__ float SIG(float v) {
    return 1.f / (1.f + __expf(-v));
}

// G=2 dual-output single-chain 50-dot: activations loaded once
// (12 LDS.128 + 1 LDS.64), reused for both output columns (50 fma.f32x2).
__device__ __forceinline__ void dot50x2_1c(const float* __restrict__ ax,
                                           const ull* __restrict__ w1,
                                           const ull* __restrict__ w2,
                                           float& o0, float& o1) {
    ull a0 = 0, a1 = 0, b0 = 0, b1 = 0;
#pragma unroll
    for (int j = 0; j < 6; j++) {
        ulonglong2 v0 = *(const ulonglong2*)(ax + 8 * j);
        ulonglong2 v1 = *(const ulonglong2*)(ax + 8 * j + 4);
        a0 = FMA2(w1[4 * j + 0], v0.x, a0);
        a1 = FMA2(w1[4 * j + 1], v0.y, a1);
        a0 = FMA2(w1[4 * j + 2], v1.x, a0);
        a1 = FMA2(w1[4 * j + 3], v1.y, a1);
        b0 = FMA2(w2[4 * j + 0], v0.x, b0);
        b1 = FMA2(w2[4 * j + 1], v0.y, b1);
        b0 = FMA2(w2[4 * j + 2], v1.x, b0);
        b1 = FMA2(w2[4 * j + 3], v1.y, b1);
    }
    ull tv = *(const ull*)(ax + 48);
    a0 = FMA2(w1[24], tv, a0);
    b0 = FMA2(w2[24], tv, b0);
    o0 = HSUM2(a0, a1);
    o1 = HSUM2(b0, b1);
}

// ---------------------------------------------------------------------------
// k01: merged constant folding (k0 role, 32 blocks) + vocab tables
// (k1 role, 3750 blocks x 8 vocab rows).  Unchanged from R10.
// ---------------------------------------------------------------------------
__global__ void __launch_bounds__(160)
k01(const float* __restrict__ C_embed, const float* __restrict__ C_w,
    const float* __restrict__ S1w, const float* __restrict__ S2w,
    const float* __restrict__ WW, const float* __restrict__ hT,
    const float* __restrict__ S2,
    const float* __restrict__ W_embed, const float* __restrict__ embed_r,
    const float* __restrict__ V_embed, const float* __restrict__ beta,
    const float* __restrict__ Wrs1, const float* __restrict__ bs1) {
    __shared__ float sm[VR * DN + VR * RN];
    __shared__ float k0sm[2 * RN + 2 * RWN];
    int t = threadIdx.x;

    if (blockIdx.x >= K1BLOCKS) {
        float* cvs = k0sm;
        float* u   = k0sm + RN;
        float* cw  = k0sm + 2 * RN;
        float* uw  = k0sm + 2 * RN + RWN;
        if (t < RN) {
            float s = 0.f;
#pragma unroll
            for (int c = 0; c < CN; c++) s += C_embed[c * RN + t];
            cvs[t] = s;
            float su = 0.f;
#pragma unroll
            for (int s2 = 0; s2 < SN; s2++) su += hT[s2] * S2[s2 * RN + t];
            u[t] = su;
        }
        if (t < RWN) {
            float s = 0.f;
#pragma unroll
            for (int c = 0; c < CN; c++) s += C_w[c * RWN + t];
            cw[t] = s;
            float su = 0.f;
#pragma unroll
            for (int s2 = 0; s2 < SN; s2++) su += hT[s2] * S2w[s2 * RWN + t];
            uw[t] = su;
        }
        __syncthreads();

        const int N_WLD = SN * SN;
        const int N_S2C = RN * SN;
        const int N_SC  = CN * 200;
        const int TOT = N_WLD + N_S2C + N_SC;
        int bid = blockIdx.x - K1BLOCKS;
        int stride = K0BLOCKS * 160;
        for (int g = bid * 160 + t; g < TOT; g += stride) {
            int i = g;
            if (i < N_WLD) {
                int s = i / SN, tt = i % SN;
                float acc = WW[i];
#pragma unroll
                for (int r = 0; r < RWN; r++)
                    acc += S1w[s * RWN + r] * cw[r] * S2w[tt * RWN + r];
                g_wild[i] = acc;
                continue;
            }
            i -= N_WLD;
            if (i < N_S2C) {
                int r = i / SN, tt = i % SN;
                g_S2cT[i] = S2[tt * RN + r] * cvs[r];
                continue;
            }
            i -= N_S2C;
            {
                int c = i / 200, k = i % 200;
                g_SC[i] = (k < RN) ? C_embed[c * RN + k] * u[k]
                                   : C_w[c * RWN + (k - RN)] * uw[k - RN];
            }
        }
        return;
    }

    float* w8 = sm;
    float (*q8)[RN] = (float (*)[RN])(sm + VR * DN);
    int v0 = blockIdx.x * VR;

    for (int i = t; i < VR * DN; i += 160)
        w8[i] = W_embed[v0 * DN + i];
    __syncthreads();

    if (t < RN) {
        float cv = 0.f;
#pragma unroll
        for (int c = 0; c < CN; c++) cv += C_embed[c * RN + t];

        float acc[VR];
#pragma unroll
        for (int r = 0; r < VR; r++) acc[r] = 0.f;
#pragma unroll 2
        for (int d = 0; d < DN; d++) {
            float e = embed_r[d * RN + t];
#pragma unroll
            for (int r = 0; r < VR; r++) acc[r] += e * w8[r * DN + d];
        }
        float b = beta[t];
#pragma unroll
        for (int r = 0; r < VR; r++) {
            float th;
            asm("tanh.approx.f32 %0, %1;" : "=f"(th) : "f"(acc[r]));
            float tv = V_embed[(v0 + r) * RN + t] * b + th * (1.f - b);
            g_Tv[(v0 + r) * RN + t] = tv;
            q8[r][t] = tv * cv;
        }
    }
    __syncthreads();

    if (t < SN) {
        float acc[VR];
#pragma unroll
        for (int r = 0; r < VR; r++) acc[r] = 0.f;
#pragma unroll 2
        for (int d = 0; d < RN; d++) {
            float wv = Wrs1[d * SN + t];
#pragma unroll
            for (int r = 0; r < VR; r++) acc[r] += wv * q8[r][d];
        }
        float bb = bs1[t];
#pragma unroll
        for (int r = 0; r < VR; r++)
            g_Trw[(v0 + r) * SN + t] = bb + acc[r];
    }
}

// ---------------------------------------------------------------------------
// k2: sequential recurrence. 256 CTAs x 288 threads, ONE chain per CTA,
// __launch_bounds__(288, 2) -> 2 CTAs resident per SM; independent CTAs
// interleave on the SMSPs and hide each other's barrier/scoreboard stalls.
//
// Warp-specialized, G=2 (identical role math to R10, single chain):
//   warps 0-3 (t<125 active): phase-1 — 2 full 50-dots over h per thread;
//     writes p/aw/gz directly; prefetches next step's Tv/Trw in interval B.
//   warps 4-8 (i=t-128, 140 active): phase-2 — chunk q=i&3 of outputs
//     o0=2*(i>>2), o0+1 (h_new or score); 4 partials reduced via
//     shfl_xor(1,2); lane q==0 blends gate / writes scores. Loads next
//     token in interval A.
//
// Shared windows (stride WIN=68 floats, pairwise distinct mod 128B):
//   h0 @0, h1 @WIN (double buffer), p0/p1/p2 @(2..4)*WIN, aw @5*WIN.
// 2 barriers/step.
// ---------------------------------------------------------------------------
__global__ void __launch_bounds__(288, 2)
k2_recur(const int* __restrict__ tokens,
         const float* __restrict__ S1,
         const float* __restrict__ S1w,
         const float* __restrict__ Wss1,
         const float* __restrict__ h0,
         const float* __restrict__ prio_a,
         const float* __restrict__ prio_b,
         float* __restrict__ out) {
    __shared__ __align__(16) float act[6 * WIN];
    __shared__ __align__(16) float gz[SN];
    __shared__ int s_ntok;

    int t = threadIdx.x;
    int b = blockIdx.x;
    int tb = b * LN;
    long ob = (long)b * LN * CN;

    ull w1[25], w2[25];
#pragma unroll
    for (int j = 0; j < 25; j++) { w1[j] = 0ull; w2[j] = 0ull; }

    const bool isP1 = (t < 128);

    // phase-1 role state
    int fam = 3;          // 0=p, 1=aw, 2=gate, 3=inactive
    int p1w = 0;
    int out0 = 0;
    // phase-2 role state
    int o0 = 0;
    bool isScore = false, winIsH = false, p2w = false;
    int winOff = 0;
    float2 paA = make_float2(0.f, 0.f), pbA = make_float2(0.f, 0.f);

    if (isP1) {
        if (t < 125) {
            out0 = 2 * t;
            const float* mA;
            int strA, col0;
            if (out0 < 150)      { fam = 0; mA = S1;   strA = RN;  col0 = out0;
                                   p1w = (2 + out0 / 50) * WIN + (out0 % 50); }
            else if (out0 < 200) { fam = 1; mA = S1w;  strA = RWN; col0 = out0 - 150;
                                   p1w = 5 * WIN + (out0 - 150); }
            else                 { fam = 2; mA = Wss1; strA = SN;  col0 = out0 - 200; }
#pragma unroll
            for (int j = 0; j < 25; j++) {
                w1[j] = PACK2(mA[(2 * j) * strA + col0],
                              mA[(2 * j + 1) * strA + col0]);
                w2[j] = PACK2(mA[(2 * j) * strA + col0 + 1],
                              mA[(2 * j + 1) * strA + col0 + 1]);
            }
        }
    } else {
        int i = t - 128;
        int q2 = i & 3;
        int og = i >> 2;
        o0 = 2 * og;
        p2w = (q2 == 0) && (i < 140);
        if (og < 25) {
            if (q2 < 3) {
                const float* P = g_S2cT + q2 * 50 * SN;
                winOff = (2 + q2) * WIN;
#pragma unroll
                for (int j = 0; j < 25; j++) {
                    w1[j] = PACK2(P[(2 * j) * SN + o0], P[(2 * j + 1) * SN + o0]);
                    w2[j] = PACK2(P[(2 * j) * SN + o0 + 1], P[(2 * j + 1) * SN + o0 + 1]);
                }
            } else {
                winIsH = true;
#pragma unroll
                for (int j = 0; j < 25; j++) {
                    w1[j] = PACK2(g_wild[(2 * j) * SN + o0], g_wild[(2 * j + 1) * SN + o0]);
                    w2[j] = PACK2(g_wild[(2 * j) * SN + o0 + 1], g_wild[(2 * j + 1) * SN + o0 + 1]);
                }
            }
        } else if (og < 35) {
            isScore = true;
            int c0 = o0 - 50;
            int off = (q2 < 3) ? q2 * 50 : 150;
            winOff = (q2 < 3) ? (2 + q2) * WIN : 5 * WIN;
#pragma unroll
            for (int j = 0; j < 25; j++) {
                w1[j] = PACK2(g_SC[c0 * 200 + off + 2 * j],
                              g_SC[c0 * 200 + off + 2 * j + 1]);
                w2[j] = PACK2(g_SC[(c0 + 1) * 200 + off + 2 * j],
                              g_SC[(c0 + 1) * 200 + off + 2 * j + 1]);
            }
            if (p2w) {
                paA = make_float2(prio_a[c0], prio_a[c0 + 1]);
                pbA = make_float2(prio_b[c0], prio_b[c0 + 1]);
            }
        }
    }

    // ---- init: state + prime step-0 gathers ----
    if (t < SN) act[t] = h0[t];
    float2 tvA = make_float2(0.f, 0.f), trA = tvA;
    if (isP1 && fam != 3) {
        int t0 = tokens[tb];
        if (fam == 0)      tvA = *(const float2*)&g_Tv[t0 * RN + out0];
        else if (fam == 2) trA = *(const float2*)&g_Trw[t0 * SN + (out0 - 200)];
    }
    __syncthreads();

    for (int l = 0; l < LN; l++) {
        int hc = (l & 1) ? WIN : 0;

        // ----------- interval A: phase-1 compute | token preload -----------
        if (isP1) {
            if (fam != 3) {
                float o0v, o1v;
                dot50x2_1c(act + hc, w1, w2, o0v, o1v);
                if (fam == 0) {
                    *(float2*)&act[p1w] = make_float2(o0v * tvA.x, o1v * tvA.y);
                } else if (fam == 1) {
                    *(float2*)&act[p1w] = make_float2(o0v, o1v);
                } else {
                    *(float2*)&gz[out0 - 200] =
                        make_float2(SIG(o0v + trA.x), SIG(o1v + trA.y));
                }
            }
        } else if (t == 128) {
            int nl = (l + 1 < LN) ? l + 1 : l;
            s_ntok = tokens[tb + nl];
        }
        __syncthreads();

        // --------- interval B: phase-2 compute | Tv/Trw prefetch -----------
        if (isP1) {
            if (fam == 0) {
                tvA = *(const float2*)&g_Tv[s_ntok * RN + out0];
            } else if (fam == 2) {
                trA = *(const float2*)&g_Trw[s_ntok * SN + (out0 - 200)];
            }
        } else {
            int aw2 = winIsH ? hc : winOff;
            float s0, s1;
            dot50x2_1c(act + aw2, w1, w2, s0, s1);

            s0 += __shfl_xor_sync(0xffffffffu, s0, 1);
            s0 += __shfl_xor_sync(0xffffffffu, s0, 2);
            s1 += __shfl_xor_sync(0xffffffffu, s1, 1);
            s1 += __shfl_xor_sync(0xffffffffu, s1, 2);

            if (p2w) {
                if (!isScore) {
                    int hn = WIN - hc;
                    float2 hx = *(const float2*)&act[hc + o0];
                    float2 z  = *(const float2*)&gz[o0];
                    *(float2*)&act[hn + o0] = make_float2(
                        z.x * s0 + (1.f - z.x) * hx.x,
                        z.y * s1 + (1.f - z.y) * hx.y);
                } else {
                    int c0 = o0 - 50;
                    *(float2*)(out + ob + (long)l * CN + c0) =
                        make_float2(s0 * paA.x + pbA.x, s1 * paA.y + pbA.y);
                }
            }
        }
        __syncthreads();
    }
}

// ---------------------------------------------------------------------------
// Launch. Inputs (metadata order): tokens, W_embed, embed_r, V_embed,
// C_embed, S1, S2, S1_w, S2_w, C_w, WW, h0, hT, beta_vec, Wss1, Wrs1, bs1,
// prio_a, prio_b
// ---------------------------------------------------------------------------
extern "C" void kernel_launch(void* const* d_in, const int* in_sizes, int n_in,
                              void* d_out, int out_size) {
    const int*   tokens  = (const int*)  d_in[0];
    const float* W_embed = (const float*)d_in[1];
    const float* embed_r = (const float*)d_in[2];
    const float* V_embed = (const float*)d_in[3];
    const float* C_embed = (const float*)d_in[4];
    const float* S1      = (const float*)d_in[5];
    const float* S2      = (const float*)d_in[6];
    const float* S1_w    = (const float*)d_in[7];
    const float* S2_w    = (const float*)d_in[8];
    const float* C_w     = (const float*)d_in[9];
    const float* WW      = (const float*)d_in[10];
    const float* h0      = (const float*)d_in[11];
    const float* hT      = (const float*)d_in[12];
    const float* beta    = (const float*)d_in[13];
    const float* Wss1    = (const float*)d_in[14];
    const float* Wrs1    = (const float*)d_in[15];
    const float* bs1     = (const float*)d_in[16];
    const float* prio_a  = (const float*)d_in[17];
    const float* prio_b  = (const float*)d_in[18];
    float* out = (float*)d_out;

    k01<<<K1BLOCKS + K0BLOCKS, 160>>>(C_embed, C_w, S1_w, S2_w, WW, hT, S2,
                                      W_embed, embed_r, V_embed, beta, Wrs1, bs1);
    k2_recur<<<BN, 288>>>(tokens, S1, S1_w, Wss1, h0, prio_a, prio_b, out);
}

// round 12
// speedup vs baseline: 1.9064x; 1.9064x over previous
#include <cuda_runtime.h>
#include <math.h>

#define VOCABN 30000
#define DN 100
#define RN 150
#define RWN 50
#define SN 50
#define CN 20
#define BN 256
#define LN 512
#define VR 16                     // vocab rows per k1-role block
#define K1BLOCKS (VOCABN / VR)    // 1875
#define K0BLOCKS 32
#define WIN 68                    // k2 shared window stride (272B)
#define PHW 200                   // per-(b,l) row: p[0:150] | h[150:200]

typedef unsigned long long ull;

// ---- folded constants / tables / deferred-score buffer (static device) ----
__device__ float g_Tv[VOCABN * RN];    // blended V embedding per vocab id
__device__ float g_Trw[VOCABN * SN];   // (Tv*Cvs)@Wrs1 + bs1 per vocab id
__device__ float g_wild[SN * SN];      // [s][t]
__device__ float g_S2cT[RN * SN];      // S2[t][r]*Cvs[r], stored [r][t]
__device__ float g_SCf[PHW * CN];      // [k][c] score matrix (prio_a folded)
__device__ float g_PH[(size_t)BN * LN * PHW];  // p|h per (b,l)  (~105 MB)

// ---- packed f32x2 helpers ----
__device__ __forceinline__ ull FMA2(ull a, ull b, ull c) {
    ull d;
    asm("fma.rn.f32x2 %0, %1, %2, %3;" : "=l"(d) : "l"(a), "l"(b), "l"(c));
    return d;
}
__device__ __forceinline__ float HSUM2(ull a, ull b) {
    union { ull u; float2 f; } x, y;
    x.u = a; y.u = b;
    return (x.f.x + x.f.y) + (y.f.x + y.f.y);
}
__device__ __forceinline__ ull PACK2(float a, float b) {
    union { ull u; float2 f; } x;
    x.f = make_float2(a, b);
    return x.u;
}
__device__ __forceinline__ float SIG(float v) {
    return 1.f / (1.f + __expf(-v));
}

// Single-output, dual-chain 50-dot: per chain 12 LDS.128 + 1 LDS.64,
// 25 fma.f32x2; chains interleaved for ILP.
__device__ __forceinline__ void dot50_2c(const float* __restrict__ ax,
                                         const float* __restrict__ ay,
                                         const ull* __restrict__ w,
                                         float& ox, float& oy) {
    ull a0 = 0, a1 = 0, b0 = 0, b1 = 0;
#pragma unroll
    for (int j = 0; j < 6; j++) {
        ulonglong2 vx0 = *(const ulonglong2*)(ax + 8 * j);
        ulonglong2 vx1 = *(const ulonglong2*)(ax + 8 * j + 4);
        ulonglong2 vy0 = *(const ulonglong2*)(ay + 8 * j);
        ulonglong2 vy1 = *(const ulonglong2*)(ay + 8 * j + 4);
        a0 = FMA2(w[4 * j + 0], vx0.x, a0);
        a1 = FMA2(w[4 * j + 1], vx0.y, a1);
        a0 = FMA2(w[4 * j + 2], vx1.x, a0);
        a1 = FMA2(w[4 * j + 3], vx1.y, a1);
        b0 = FMA2(w[4 * j + 0], vy0.x, b0);
        b1 = FMA2(w[4 * j + 1], vy0.y, b1);
        b0 = FMA2(w[4 * j + 2], vy1.x, b0);
        b1 = FMA2(w[4 * j + 3], vy1.y, b1);
    }
    a0 = FMA2(w[24], *(const ull*)(ax + 48), a0);
    b0 = FMA2(w[24], *(const ull*)(ay + 48), b0);
    ox = HSUM2(a0, a1);
    oy = HSUM2(b0, b1);
}

// ---------------------------------------------------------------------------
// k01: merged constant folding (k0 role, 32 blocks) + vocab tables
// (k1 role, 1875 blocks x 16 vocab rows).
// ---------------------------------------------------------------------------
__global__ void __launch_bounds__(160)
k01(const float* __restrict__ C_embed, const float* __restrict__ C_w,
    const float* __restrict__ S1w, const float* __restrict__ S2w,
    const float* __restrict__ WW, const float* __restrict__ hT,
    const float* __restrict__ S2, const float* __restrict__ prio_a,
    const float* __restrict__ W_embed, const float* __restrict__ embed_r,
    const float* __restrict__ V_embed, const float* __restrict__ beta,
    const float* __restrict__ Wrs1, const float* __restrict__ bs1) {
    __shared__ float sm[VR * DN + VR * RN];
    __shared__ float k0sm[2 * RN + 2 * RWN];
    int t = threadIdx.x;

    if (blockIdx.x >= K1BLOCKS) {
        // ---------------- k0 role ----------------
        float* cvs = k0sm;
        float* u   = k0sm + RN;
        float* cw  = k0sm + 2 * RN;
        float* uw  = k0sm + 2 * RN + RWN;
        if (t < RN) {
            float s = 0.f;
#pragma unroll
            for (int c = 0; c < CN; c++) s += C_embed[c * RN + t];
            cvs[t] = s;
            float su = 0.f;
#pragma unroll
            for (int s2 = 0; s2 < SN; s2++) su += hT[s2] * S2[s2 * RN + t];
            u[t] = su;
        }
        if (t < RWN) {
            float s = 0.f;
#pragma unroll
            for (int c = 0; c < CN; c++) s += C_w[c * RWN + t];
            cw[t] = s;
            float su = 0.f;
#pragma unroll
            for (int s2 = 0; s2 < SN; s2++) su += hT[s2] * S2w[s2 * RWN + t];
            uw[t] = su;
        }
        __syncthreads();

        const int N_WLD = SN * SN;      // 2500
        const int N_S2C = RN * SN;      // 7500
        const int N_SCF = PHW * CN;     // 4000
        const int TOT = N_WLD + N_S2C + N_SCF;
        int bid = blockIdx.x - K1BLOCKS;
        int stride = K0BLOCKS * 160;
        for (int g = bid * 160 + t; g < TOT; g += stride) {
            int i = g;
            if (i < N_WLD) {
                int s = i / SN, tt = i % SN;
                float acc = WW[i];
#pragma unroll
                for (int r = 0; r < RWN; r++)
                    acc += S1w[s * RWN + r] * cw[r] * S2w[tt * RWN + r];
                g_wild[i] = acc;
                continue;
            }
            i -= N_WLD;
            if (i < N_S2C) {
                int r = i / SN, tt = i % SN;
                g_S2cT[i] = S2[tt * RN + r] * cvs[r];
                continue;
            }
            i -= N_S2C;
            {
                int k = i / CN, c = i % CN;
                float v;
                if (k < RN) {
                    v = C_embed[c * RN + k] * u[k];
                } else {
                    int s = k - RN;
                    float acc = 0.f;
#pragma unroll
                    for (int r = 0; r < RWN; r++)
                        acc += S1w[s * RWN + r] * uw[r] * C_w[c * RWN + r];
                    v = acc;
                }
                g_SCf[i] = v * prio_a[c];
            }
        }
        return;
    }

    // ---------------- k1 role ----------------
    float* wR = sm;
    float (*qR)[RN] = (float (*)[RN])(sm + VR * DN);
    int v0 = blockIdx.x * VR;

    for (int i = t; i < VR * DN; i += 160)
        wR[i] = W_embed[v0 * DN + i];
    __syncthreads();

    if (t < RN) {
        float cv = 0.f;
#pragma unroll
        for (int c = 0; c < CN; c++) cv += C_embed[c * RN + t];

        float acc[VR];
#pragma unroll
        for (int r = 0; r < VR; r++) acc[r] = 0.f;
#pragma unroll 2
        for (int d = 0; d < DN; d++) {
            float e = embed_r[d * RN + t];
#pragma unroll
            for (int r = 0; r < VR; r++) acc[r] += e * wR[r * DN + d];
        }
        float b = beta[t];
#pragma unroll
        for (int r = 0; r < VR; r++) {
            float th;
            asm("tanh.approx.f32 %0, %1;" : "=f"(th) : "f"(acc[r]));
            float tv = V_embed[(v0 + r) * RN + t] * b + th * (1.f - b);
            g_Tv[(v0 + r) * RN + t] = tv;
            qR[r][t] = tv * cv;
        }
    }
    __syncthreads();

    if (t < SN) {
        float acc[VR];
#pragma unroll
        for (int r = 0; r < VR; r++) acc[r] = 0.f;
#pragma unroll 2
        for (int d = 0; d < RN; d++) {
            float wv = Wrs1[d * SN + t];
#pragma unroll
            for (int r = 0; r < VR; r++) acc[r] += wv * qR[r][d];
        }
        float bb = bs1[t];
#pragma unroll
        for (int r = 0; r < VR; r++)
            g_Trw[(v0 + r) * SN + t] = bb + acc[r];
    }
}

// ---------------------------------------------------------------------------
// k2: sequential recurrence, SCORE-DEFERRED. 128 CTAs x 448 threads (14
// warps), 2 chains/CTA (SoA act_x/act_y), G=1 both phases (25 ull weights
// per thread -> no spills, short per-warp paths, 1.75 active warps/SMSP).
//
//   phase-1 (warps 0-6, t<200 active): out t<150 -> p[t]=(h@S1)[t]*Tv;
//     t in [150,200) -> gate gz. Interval B: store p to g_PH + prefetch
//     Tv/Trw for next token.
//   phase-2 (warps 7-13, i=t-224<200 active): h_new chunk q=i&3 of output
//     o=i>>2 (q<3: S2cT over p-window; q=3: wild over live h). shfl_xor(1,2)
//     reduce; lane q==0 blends gate, writes h double-buffered. Interval A:
//     i<50 stores h_l to g_PH; i==200/201 load next tokens.
//
// Shared windows (stride WIN=68 floats; pairwise distinct mod 128B):
//   h0 @0, h1 @WIN, p0/p1/p2 @(2..4)*WIN.  2 barriers/step.
// ---------------------------------------------------------------------------
__global__ void __launch_bounds__(448, 1)
k2_recur(const int* __restrict__ tokens,
         const float* __restrict__ S1,
         const float* __restrict__ Wss1,
         const float* __restrict__ h0,
         float* __restrict__ out_unused) {
    __shared__ __align__(16) float act_x[5 * WIN];
    __shared__ __align__(16) float act_y[5 * WIN];
    __shared__ __align__(8) float2 gz[SN];
    __shared__ int s_ntok[2];

    int t = threadIdx.x;
    int b0 = blockIdx.x * 2;
    int b1 = b0 + 1;
    int tb0 = b0 * LN, tb1 = b1 * LN;
    long rb0 = (long)b0 * LN, rb1 = (long)b1 * LN;   // PH row bases

    ull w[25];
#pragma unroll
    for (int j = 0; j < 25; j++) w[j] = 0ull;

    const bool isP1 = (t < 224);

    // phase-1 role
    int fam = 3;               // 0=p, 1=gate, 3=inactive
    int p1w = 0;
    // phase-2 role
    int o2 = 0;
    bool winIsH = false, p2w = false;
    int winOff = 2 * WIN;

    if (isP1) {
        if (t < 150) {
            fam = 0;
            p1w = (2 + t / 50) * WIN + (t % 50);
#pragma unroll
            for (int j = 0; j < 25; j++)
                w[j] = PACK2(S1[(2 * j) * RN + t], S1[(2 * j + 1) * RN + t]);
        } else if (t < 200) {
            fam = 1;
            int col = t - 150;
#pragma unroll
            for (int j = 0; j < 25; j++)
                w[j] = PACK2(Wss1[(2 * j) * SN + col],
                             Wss1[(2 * j + 1) * SN + col]);
        }
    } else {
        int i = t - 224;
        if (i < 200) {
            int q = i & 3;
            o2 = i >> 2;
            p2w = (q == 0);
            if (q < 3) {
                const float* P = g_S2cT + q * 50 * SN;
                winOff = (2 + q) * WIN;
#pragma unroll
                for (int j = 0; j < 25; j++)
                    w[j] = PACK2(P[(2 * j) * SN + o2], P[(2 * j + 1) * SN + o2]);
            } else {
                winIsH = true;
#pragma unroll
                for (int j = 0; j < 25; j++)
                    w[j] = PACK2(g_wild[(2 * j) * SN + o2],
                                 g_wild[(2 * j + 1) * SN + o2]);
            }
        }
    }

    // ---- init: state + prime step-0 gathers ----
    if (t < SN) { float h = h0[t]; act_x[t] = h; act_y[t] = h; }
    float tvx = 0.f, tvy = 0.f, trx = 0.f, tryy = 0.f;
    if (fam == 0) {
        int t0 = tokens[tb0], t1 = tokens[tb1];
        tvx = g_Tv[t0 * RN + t];
        tvy = g_Tv[t1 * RN + t];
    } else if (fam == 1) {
        int t0 = tokens[tb0], t1 = tokens[tb1];
        trx  = g_Trw[t0 * SN + (t - 150)];
        tryy = g_Trw[t1 * SN + (t - 150)];
    }
    __syncthreads();

    for (int l = 0; l < LN; l++) {
        int hc = (l & 1) ? WIN : 0;
        float pxv = 0.f, pyv = 0.f;     // p values kept for the gmem store

        // -------- interval A: phase-1 compute | h-store + token preload -----
        if (isP1) {
            if (fam != 3) {
                float ox, oy;
                dot50_2c(act_x + hc, act_y + hc, w, ox, oy);
                if (fam == 0) {
                    pxv = ox * tvx;
                    pyv = oy * tvy;
                    act_x[p1w] = pxv;
                    act_y[p1w] = pyv;
                } else {
                    gz[t - 150] = make_float2(SIG(ox + trx), SIG(oy + tryy));
                }
            }
        } else {
            int i = t - 224;
            if (i < 50) {
                g_PH[(rb0 + l) * PHW + 150 + i] = act_x[hc + i];
                g_PH[(rb1 + l) * PHW + 150 + i] = act_y[hc + i];
            } else if (i == 200) {
                int nl = (l + 1 < LN) ? l + 1 : l;
                s_ntok[0] = tokens[tb0 + nl];
            } else if (i == 201) {
                int nl = (l + 1 < LN) ? l + 1 : l;
                s_ntok[1] = tokens[tb1 + nl];
            }
        }
        __syncthreads();

        // -------- interval B: phase-2 compute | p-store + prefetch ----------
        if (isP1) {
            if (fam == 0) {
                g_PH[(rb0 + l) * PHW + t] = pxv;
                g_PH[(rb1 + l) * PHW + t] = pyv;
                int n0 = s_ntok[0], n1 = s_ntok[1];
                tvx = g_Tv[n0 * RN + t];
                tvy = g_Tv[n1 * RN + t];
            } else if (fam == 1) {
                int n0 = s_ntok[0], n1 = s_ntok[1];
                trx  = g_Trw[n0 * SN + (t - 150)];
                tryy = g_Trw[n1 * SN + (t - 150)];
            }
        } else {
            int aw2 = winIsH ? hc : winOff;
            float sx, sy;
            dot50_2c(act_x + aw2, act_y + aw2, w, sx, sy);

            sx += __shfl_xor_sync(0xffffffffu, sx, 1);
            sx += __shfl_xor_sync(0xffffffffu, sx, 2);
            sy += __shfl_xor_sync(0xffffffffu, sy, 1);
            sy += __shfl_xor_sync(0xffffffffu, sy, 2);

            if (p2w) {
                int hn = WIN - hc;
                float2 z = gz[o2];
                float hx = act_x[hc + o2], hy = act_y[hc + o2];
                act_x[hn + o2] = z.x * sx + (1.f - z.x) * hx;
                act_y[hn + o2] = z.y * sy + (1.f - z.y) * hy;
            }
        }
        __syncthreads();
    }
}

// ---------------------------------------------------------------------------
// k3: deferred scores. out[row][c] = [p|h](row) @ SCf + prio_b.
// 512 blocks x 256 threads, one row per thread; SCf broadcast from shared.
// ---------------------------------------------------------------------------
__global__ void __launch_bounds__(256)
k3_score(const float* __restrict__ prio_b, float* __restrict__ out) {
    __shared__ __align__(16) float sc[PHW * CN];
    int t = threadIdx.x;
    for (int i = t; i < PHW * CN; i += 256) sc[i] = g_SCf[i];
    __syncthreads();

    long row = (long)blockIdx.x * 256 + t;
    const float* ph = g_PH + row * PHW;

    ull acc[10];
#pragma unroll
    for (int c = 0; c < 10; c++) acc[c] = 0ull;

#pragma unroll 4
    for (int k = 0; k < PHW; k += 4) {
        float4 v = *(const float4*)(ph + k);
        const ull* s0 = (const ull*)(sc + (k + 0) * CN);
        const ull* s1 = (const ull*)(sc + (k + 1) * CN);
        const ull* s2 = (const ull*)(sc + (k + 2) * CN);
        const ull* s3 = (const ull*)(sc + (k + 3) * CN);
        ull v0 = PACK2(v.x, v.x), v1 = PACK2(v.y, v.y);
        ull v2 = PACK2(v.z, v.z), v3 = PACK2(v.w, v.w);
#pragma unroll
        for (int c = 0; c < 10; c++) {
            acc[c] = FMA2(s0[c], v0, acc[c]);
            acc[c] = FMA2(s1[c], v1, acc[c]);
            acc[c] = FMA2(s2[c], v2, acc[c]);
            acc[c] = FMA2(s3[c], v3, acc[c]);
        }
    }

    float* o = out + row * CN;
#pragma unroll
    for (int c = 0; c < 10; c++) {
        union { ull u; float2 f; } a;
        a.u = acc[c];
        float2 pb = *(const float2*)(prio_b + 2 * c);
        *(float2*)(o + 2 * c) = make_float2(a.f.x + pb.x, a.f.y + pb.y);
    }
}

// ---------------------------------------------------------------------------
// Launch. Inputs (metadata order): tokens, W_embed, embed_r, V_embed,
// C_embed, S1, S2, S1_w, S2_w, C_w, WW, h0, hT, beta_vec, Wss1, Wrs1, bs1,
// prio_a, prio_b
// ---------------------------------------------------------------------------
extern "C" void kernel_launch(void* const* d_in, const int* in_sizes, int n_in,
                              void* d_out, int out_size) {
    const int*   tokens  = (const int*)  d_in[0];
    const float* W_embed = (const float*)d_in[1];
    const float* embed_r = (const float*)d_in[2];
    const float* V_embed = (const float*)d_in[3];
    const float* C_embed = (const float*)d_in[4];
    const float* S1      = (const float*)d_in[5];
    const float* S2      = (const float*)d_in[6];
    const float* S1_w    = (const float*)d_in[7];
    const float* S2_w    = (const float*)d_in[8];
    const float* C_w     = (const float*)d_in[9];
    const float* WW      = (const float*)d_in[10];
    const float* h0      = (const float*)d_in[11];
    const float* hT      = (const float*)d_in[12];
    const float* beta    = (const float*)d_in[13];
    const float* Wss1    = (const float*)d_in[14];
    const float* Wrs1    = (const float*)d_in[15];
    const float* bs1     = (const float*)d_in[16];
    const float* prio_a  = (const float*)d_in[17];
    const float* prio_b  = (const float*)d_in[18];
    float* out = (float*)d_out;

    k01<<<K1BLOCKS + K0BLOCKS, 160>>>(C_embed, C_w, S1_w, S2_w, WW, hT, S2,
                                      prio_a, W_embed, embed_r, V_embed, beta,
                                      Wrs1, bs1);
    k2_recur<<<BN / 2, 448>>>(tokens, S1, Wss1, h0, out);
    k3_score<<<(BN * LN) / 256, 256>>>(prio_b, out);
}

// round 13
// speedup vs baseline: 2.0219x; 1.0605x over previous
#include <cuda_runtime.h>
#include <math.h>

#define VOCABN 30000
#define DN 100
#define RN 150
#define RWN 50
#define SN 50
#define CN 20
#define BN 256
#define LN 512
#define VR 8                      // vocab rows per k1-role block
#define K1BLOCKS (VOCABN / VR)    // 3750
#define K0BLOCKS 32
#define WIN 68                    // k2 shared window stride (272B)
#define PHW 200                   // per-(b,l) row: p[0:150] | h[150:200]

typedef unsigned long long ull;

// ---- folded constants / tables / deferred-score buffer (static device) ----
__device__ float g_Tv[VOCABN * RN];    // blended V embedding per vocab id
__device__ float g_Trw[VOCABN * SN];   // (Tv*Cvs)@Wrs1 + bs1 per vocab id
__device__ float g_wild[SN * SN];      // [s][t]
__device__ float g_S2cT[RN * SN];      // S2[t][r]*Cvs[r], stored [r][t]
__device__ float g_SCf[PHW * CN];      // [k][c] score matrix (prio_a folded)
__device__ float g_PH[(size_t)BN * LN * PHW];  // p|h per (b,l)  (~105 MB)

// ---- packed f32x2 helpers ----
__device__ __forceinline__ ull FMA2(ull a, ull b, ull c) {
    ull d;
    asm("fma.rn.f32x2 %0, %1, %2, %3;" : "=l"(d) : "l"(a), "l"(b), "l"(c));
    return d;
}
__device__ __forceinline__ float HSUM2(ull a, ull b) {
    union { ull u; float2 f; } x, y;
    x.u = a; y.u = b;
    return (x.f.x + x.f.y) + (y.f.x + y.f.y);
}
__device__ __forceinline__ ull PACK2(float a, float b) {
    union { ull u; float2 f; } x;
    x.f = make_float2(a, b);
    return x.u;
}
__device__ __forceinline__ float SIG(float v) {
    return 1.f / (1.f + __expf(-v));
}

// G=2 dual-output single-chain 50-dot: activations loaded once
// (12 LDS.128 + 1 LDS.64), reused for both output columns (50 fma.f32x2).
__device__ __forceinline__ void dot50x2_1c(const float* __restrict__ ax,
                                           const ull* __restrict__ w1,
                                           const ull* __restrict__ w2,
                                           float& o0, float& o1) {
    ull a0 = 0, a1 = 0, b0 = 0, b1 = 0;
#pragma unroll
    for (int j = 0; j < 6; j++) {
        ulonglong2 v0 = *(const ulonglong2*)(ax + 8 * j);
        ulonglong2 v1 = *(const ulonglong2*)(ax + 8 * j + 4);
        a0 = FMA2(w1[4 * j + 0], v0.x, a0);
        a1 = FMA2(w1[4 * j + 1], v0.y, a1);
        a0 = FMA2(w1[4 * j + 2], v1.x, a0);
        a1 = FMA2(w1[4 * j + 3], v1.y, a1);
        b0 = FMA2(w2[4 * j + 0], v0.x, b0);
        b1 = FMA2(w2[4 * j + 1], v0.y, b1);
        b0 = FMA2(w2[4 * j + 2], v1.x, b0);
        b1 = FMA2(w2[4 * j + 3], v1.y, b1);
    }
    ull tv = *(const ull*)(ax + 48);
    a0 = FMA2(w1[24], tv, a0);
    b0 = FMA2(w2[24], tv, b0);
    o0 = HSUM2(a0, a1);
    o1 = HSUM2(b0, b1);
}

// ---------------------------------------------------------------------------
// k01: merged constant folding (k0 role, 32 blocks, emits g_SCf with prio_a
// folded) + vocab tables (k1 role, 3750 blocks x 8 vocab rows).
// ---------------------------------------------------------------------------
__global__ void __launch_bounds__(160)
k01(const float* __restrict__ C_embed, const float* __restrict__ C_w,
    const float* __restrict__ S1w, const float* __restrict__ S2w,
    const float* __restrict__ WW, const float* __restrict__ hT,
    const float* __restrict__ S2, const float* __restrict__ prio_a,
    const float* __restrict__ W_embed, const float* __restrict__ embed_r,
    const float* __restrict__ V_embed, const float* __restrict__ beta,
    const float* __restrict__ Wrs1, const float* __restrict__ bs1) {
    __shared__ float sm[VR * DN + VR * RN];
    __shared__ float k0sm[2 * RN + 2 * RWN];
    int t = threadIdx.x;

    if (blockIdx.x >= K1BLOCKS) {
        // ---------------- k0 role ----------------
        float* cvs = k0sm;
        float* u   = k0sm + RN;
        float* cw  = k0sm + 2 * RN;
        float* uw  = k0sm + 2 * RN + RWN;
        if (t < RN) {
            float s = 0.f;
#pragma unroll
            for (int c = 0; c < CN; c++) s += C_embed[c * RN + t];
            cvs[t] = s;
            float su = 0.f;
#pragma unroll
            for (int s2 = 0; s2 < SN; s2++) su += hT[s2] * S2[s2 * RN + t];
            u[t] = su;
        }
        if (t < RWN) {
            float s = 0.f;
#pragma unroll
            for (int c = 0; c < CN; c++) s += C_w[c * RWN + t];
            cw[t] = s;
            float su = 0.f;
#pragma unroll
            for (int s2 = 0; s2 < SN; s2++) su += hT[s2] * S2w[s2 * RWN + t];
            uw[t] = su;
        }
        __syncthreads();

        const int N_WLD = SN * SN;      // 2500
        const int N_S2C = RN * SN;      // 7500
        const int N_SCF = PHW * CN;     // 4000
        const int TOT = N_WLD + N_S2C + N_SCF;
        int bid = blockIdx.x - K1BLOCKS;
        int stride = K0BLOCKS * 160;
        for (int g = bid * 160 + t; g < TOT; g += stride) {
            int i = g;
            if (i < N_WLD) {
                int s = i / SN, tt = i % SN;
                float acc = WW[i];
#pragma unroll
                for (int r = 0; r < RWN; r++)
                    acc += S1w[s * RWN + r] * cw[r] * S2w[tt * RWN + r];
                g_wild[i] = acc;
                continue;
            }
            i -= N_WLD;
            if (i < N_S2C) {
                int r = i / SN, tt = i % SN;
                g_S2cT[i] = S2[tt * RN + r] * cvs[r];
                continue;
            }
            i -= N_S2C;
            {
                int k = i / CN, c = i % CN;
                float v;
                if (k < RN) {
                    v = C_embed[c * RN + k] * u[k];
                } else {
                    int s = k - RN;
                    float acc = 0.f;
#pragma unroll
                    for (int r = 0; r < RWN; r++)
                        acc += S1w[s * RWN + r] * uw[r] * C_w[c * RWN + r];
                    v = acc;
                }
                g_SCf[i] = v * prio_a[c];
            }
        }
        return;
    }

    // ---------------- k1 role ----------------
    float* wR = sm;
    float (*qR)[RN] = (float (*)[RN])(sm + VR * DN);
    int v0 = blockIdx.x * VR;

    for (int i = t; i < VR * DN; i += 160)
        wR[i] = W_embed[v0 * DN + i];
    __syncthreads();

    if (t < RN) {
        float cv = 0.f;
#pragma unroll
        for (int c = 0; c < CN; c++) cv += C_embed[c * RN + t];

        float acc[VR];
#pragma unroll
        for (int r = 0; r < VR; r++) acc[r] = 0.f;
#pragma unroll 2
        for (int d = 0; d < DN; d++) {
            float e = embed_r[d * RN + t];
#pragma unroll
            for (int r = 0; r < VR; r++) acc[r] += e * wR[r * DN + d];
        }
        float b = beta[t];
#pragma unroll
        for (int r = 0; r < VR; r++) {
            float th;
            asm("tanh.approx.f32 %0, %1;" : "=f"(th) : "f"(acc[r]));
            float tv = V_embed[(v0 + r) * RN + t] * b + th * (1.f - b);
            g_Tv[(v0 + r) * RN + t] = tv;
            qR[r][t] = tv * cv;
        }
    }
    __syncthreads();

    if (t < SN) {
        float acc[VR];
#pragma unroll
        for (int r = 0; r < VR; r++) acc[r] = 0.f;
#pragma unroll 2
        for (int d = 0; d < RN; d++) {
            float wv = Wrs1[d * SN + t];
#pragma unroll
            for (int r = 0; r < VR; r++) acc[r] += wv * qR[r][d];
        }
        float bb = bs1[t];
#pragma unroll
        for (int r = 0; r < VR; r++)
            g_Trw[(v0 + r) * SN + t] = bb + acc[r];
    }
}

// ---------------------------------------------------------------------------
// k2: sequential recurrence, score-deferred. 256 CTAs x 256 threads,
// ONE chain per CTA, __launch_bounds__(256, 2) -> 2 independent CTAs per SM
// interleave through each other's barrier/latency stalls (the R10/R12
// bottleneck). G=2 everywhere (~125 natural regs, fits the 128 cap).
//
//   warps 0-3 (t<100 active): phase-1. t<75: p-pair out0=2t of S1 (G=2);
//     t in [75,100): gate pair. Interval B: store p-pair to g_PH + prefetch
//     next token's Tv/Trw.
//   warps 4-7 (i=t-128): phase-2. pair=i>>2 (h outputs o0=2*pair, o0+1),
//     chunk q=i&3 (q<3: S2cT over p-window; q=3: wild over live h).
//     ALL lanes run the dot + shfl_xor(1,2) (dummy weights for i>=100) so
//     shuffle masks stay full; lane q==0 && i<100 blends gate, writes h.
//     Interval A: i<50 stores h_l to g_PH; t==239 loads next token.
//
// Shared: h0 @0, h1 @WIN (double buffer), p0/p1/p2 @(2..4)*WIN. 2 bars/step.
// ---------------------------------------------------------------------------
__global__ void __launch_bounds__(256, 2)
k2_recur(const int* __restrict__ tokens,
         const float* __restrict__ S1,
         const float* __restrict__ Wss1,
         const float* __restrict__ h0) {
    __shared__ __align__(16) float act[5 * WIN];
    __shared__ __align__(8) float gz[SN];
    __shared__ int s_ntok;

    int t = threadIdx.x;
    int b = blockIdx.x;
    int tb = b * LN;
    long rb = (long)b * LN;          // PH row base

    ull w1[25], w2[25];
#pragma unroll
    for (int j = 0; j < 25; j++) { w1[j] = 0ull; w2[j] = 0ull; }

    const bool isP1 = (t < 128);

    // phase-1 role
    int fam = 3;               // 0=p-pair, 1=gate-pair, 3=inactive
    int out0 = 0;              // first output of the pair
    int p1w = 0;
    // phase-2 role
    int o0 = 0;
    bool winIsH = false, p2w = false;
    int winOff = 2 * WIN;

    if (isP1) {
        if (t < 75) {
            fam = 0;
            out0 = 2 * t;      // 0..148, pair never straddles a 50-block
            p1w = (2 + out0 / 50) * WIN + (out0 % 50);
#pragma unroll
            for (int j = 0; j < 25; j++) {
                w1[j] = PACK2(S1[(2 * j) * RN + out0],
                              S1[(2 * j + 1) * RN + out0]);
                w2[j] = PACK2(S1[(2 * j) * RN + out0 + 1],
                              S1[(2 * j + 1) * RN + out0 + 1]);
            }
        } else if (t < 100) {
            fam = 1;
            out0 = 2 * (t - 75);   // 0..48 (gate cols)
#pragma unroll
            for (int j = 0; j < 25; j++) {
                w1[j] = PACK2(Wss1[(2 * j) * SN + out0],
                              Wss1[(2 * j + 1) * SN + out0]);
                w2[j] = PACK2(Wss1[(2 * j) * SN + out0 + 1],
                              Wss1[(2 * j + 1) * SN + out0 + 1]);
            }
        }
    } else {
        int i = t - 128;
        int q = i & 3;
        int pair = i >> 2;
        o0 = 2 * pair;
        p2w = (q == 0) && (i < 100);
        if (i < 100) {
            if (q < 3) {
                const float* P = g_S2cT + q * 50 * SN;
                winOff = (2 + q) * WIN;
#pragma unroll
                for (int j = 0; j < 25; j++) {
                    w1[j] = PACK2(P[(2 * j) * SN + o0],
                                  P[(2 * j + 1) * SN + o0]);
                    w2[j] = PACK2(P[(2 * j) * SN + o0 + 1],
                                  P[(2 * j + 1) * SN + o0 + 1]);
                }
            } else {
                winIsH = true;
#pragma unroll
                for (int j = 0; j < 25; j++) {
                    w1[j] = PACK2(g_wild[(2 * j) * SN + o0],
                                  g_wild[(2 * j + 1) * SN + o0]);
                    w2[j] = PACK2(g_wild[(2 * j) * SN + o0 + 1],
                                  g_wild[(2 * j + 1) * SN + o0 + 1]);
                }
            }
        }
        // i >= 100: zero weights, winOff = 2*WIN (valid), writes predicated
    }

    // ---- init: state + prime step-0 gathers ----
    if (t < SN) act[t] = h0[t];
    float2 tvA = make_float2(0.f, 0.f), trA = tvA;
    if (fam == 0) {
        int t0 = tokens[tb];
        tvA = *(const float2*)&g_Tv[t0 * RN + out0];
    } else if (fam == 1) {
        int t0 = tokens[tb];
        trA = *(const float2*)&g_Trw[t0 * SN + out0];
    }
    __syncthreads();

    for (int l = 0; l < LN; l++) {
        int hc = (l & 1) ? WIN : 0;
        float pxv0 = 0.f, pxv1 = 0.f;       // p pair kept for gmem store

        // -------- interval A: phase-1 compute | h-store + token preload -----
        if (isP1) {
            if (fam != 3) {
                float v0, v1;
                dot50x2_1c(act + hc, w1, w2, v0, v1);
                if (fam == 0) {
                    pxv0 = v0 * tvA.x;
                    pxv1 = v1 * tvA.y;
                    *(float2*)&act[p1w] = make_float2(pxv0, pxv1);
                } else {
                    *(float2*)&gz[out0] =
                        make_float2(SIG(v0 + trA.x), SIG(v1 + trA.y));
                }
            }
        } else {
            int i = t - 128;
            if (i < 50) {
                g_PH[(rb + l) * PHW + 150 + i] = act[hc + i];
            } else if (t == 239) {
                int nl = (l + 1 < LN) ? l + 1 : l;
                s_ntok = tokens[tb + nl];
            }
        }
        __syncthreads();

        // -------- interval B: phase-2 compute | p-store + prefetch ----------
        if (isP1) {
            if (fam == 0) {
                *(float2*)&g_PH[(rb + l) * PHW + out0] =
                    make_float2(pxv0, pxv1);
                tvA = *(const float2*)&g_Tv[s_ntok * RN + out0];
            } else if (fam == 1) {
                trA = *(const float2*)&g_Trw[s_ntok * SN + out0];
            }
        } else {
            int aw2 = winIsH ? hc : winOff;
            float s0, s1;
            dot50x2_1c(act + aw2, w1, w2, s0, s1);

            s0 += __shfl_xor_sync(0xffffffffu, s0, 1);
            s0 += __shfl_xor_sync(0xffffffffu, s0, 2);
            s1 += __shfl_xor_sync(0xffffffffu, s1, 1);
            s1 += __shfl_xor_sync(0xffffffffu, s1, 2);

            if (p2w) {
                int hn = WIN - hc;
                float2 hx = *(const float2*)&act[hc + o0];
                float2 z  = *(const float2*)&gz[o0];
                *(float2*)&act[hn + o0] = make_float2(
                    z.x * s0 + (1.f - z.x) * hx.x,
                    z.y * s1 + (1.f - z.y) * hx.y);
            }
        }
        __syncthreads();
    }
}

// ---------------------------------------------------------------------------
// k3: deferred scores. out[row][c] = [p|h](row) @ SCf + prio_b.
// 512 blocks x 256 threads, one row per thread; SCf broadcast from shared.
// ---------------------------------------------------------------------------
__global__ void __launch_bounds__(256)
k3_score(const float* __restrict__ prio_b, float* __restrict__ out) {
    __shared__ __align__(16) float sc[PHW * CN];
    int t = threadIdx.x;
    for (int i = t; i < PHW * CN; i += 256) sc[i] = g_SCf[i];
    __syncthreads();

    long row = (long)blockIdx.x * 256 + t;
    const float* ph = g_PH + row * PHW;

    ull acc[10];
#pragma unroll
    for (int c = 0; c < 10; c++) acc[c] = 0ull;

#pragma unroll 4
    for (int k = 0; k < PHW; k += 4) {
        float4 v = *(const float4*)(ph + k);
        const ull* s0 = (const ull*)(sc + (k + 0) * CN);
        const ull* s1 = (const ull*)(sc + (k + 1) * CN);
        const ull* s2 = (const ull*)(sc + (k + 2) * CN);
        const ull* s3 = (const ull*)(sc + (k + 3) * CN);
        ull v0 = PACK2(v.x, v.x), v1 = PACK2(v.y, v.y);
        ull v2 = PACK2(v.z, v.z), v3 = PACK2(v.w, v.w);
#pragma unroll
        for (int c = 0; c < 10; c++) {
            acc[c] = FMA2(s0[c], v0, acc[c]);
            acc[c] = FMA2(s1[c], v1, acc[c]);
            acc[c] = FMA2(s2[c], v2, acc[c]);
            acc[c] = FMA2(s3[c], v3, acc[c]);
        }
    }

    float* o = out + row * CN;
#pragma unroll
    for (int c = 0; c < 10; c++) {
        union { ull u; float2 f; } a;
        a.u = acc[c];
        float2 pb = *(const float2*)(prio_b + 2 * c);
        *(float2*)(o + 2 * c) = make_float2(a.f.x + pb.x, a.f.y + pb.y);
    }
}

// ---------------------------------------------------------------------------
// Launch. Inputs (metadata order): tokens, W_embed, embed_r, V_embed,
// C_embed, S1, S2, S1_w, S2_w, C_w, WW, h0, hT, beta_vec, Wss1, Wrs1, bs1,
// prio_a, prio_b
// ---------------------------------------------------------------------------
extern "C" void kernel_launch(void* const* d_in, const int* in_sizes, int n_in,
                              void* d_out, int out_size) {
    const int*   tokens  = (const int*)  d_in[0];
    const float* W_embed = (const float*)d_in[1];
    const float* embed_r = (const float*)d_in[2];
    const float* V_embed = (const float*)d_in[3];
    const float* C_embed = (const float*)d_in[4];
    const float* S1      = (const float*)d_in[5];
    const float* S2      = (const float*)d_in[6];
    const float* S1_w    = (const float*)d_in[7];
    const float* S2_w    = (const float*)d_in[8];
    const float* C_w     = (const float*)d_in[9];
    const float* WW      = (const float*)d_in[10];
    const float* h0      = (const float*)d_in[11];
    const float* hT      = (const float*)d_in[12];
    const float* beta    = (const float*)d_in[13];
    const float* Wss1    = (const float*)d_in[14];
    const float* Wrs1    = (const float*)d_in[15];
    const float* bs1     = (const float*)d_in[16];
    const float* prio_a  = (const float*)d_in[17];
    const float* prio_b  = (const float*)d_in[18];
    float* out = (float*)d_out;

    k01<<<K1BLOCKS + K0BLOCKS, 160>>>(C_embed, C_w, S1_w, S2_w, WW, hT, S2,
                                      prio_a, W_embed, embed_r, V_embed, beta,
                                      Wrs1, bs1);
    k2_recur<<<BN, 256>>>(tokens, S1, Wss1, h0);
    k3_score<<<(BN * LN) / 256, 256>>>(prio_b, out);
}